// round 15
// baseline (speedup 1.0000x reference)
#include <cuda_runtime.h>
#include <cuda_fp16.h>
#include <math.h>

#define EMB 64
#define NLAYERS 2
#define NUx 100000
#define NIx 50000
#define ERx 1000000
#define ETx 800000
#define EPx 200000
#define HALL 192   // EMB*(1+L)
#define NBU 25     // ceil(NUx/4096)
#define NBI 13     // ceil(NIx/4096)

// ---------------- static scratch (no allocations allowed) ----------------
__device__ __half g_hu_all[(size_t)NUx * HALL];
__device__ __half g_hi_all[(size_t)NIx * HALL];
__device__ __half g_fsU_rate[(size_t)NUx * EMB];
__device__ __half g_fsU_tr[(size_t)NUx * EMB];
__device__ __half g_fsI_rb[(size_t)NIx * EMB];
__device__ float g_fdU_rb[(size_t)NUx * EMB];
__device__ float g_fdU_tr[(size_t)NUx * EMB];
__device__ float g_fdI_rate[(size_t)NIx * EMB];
__device__ float g_p[(size_t)NUx * EMB];
__device__ float g_q[(size_t)NUx * EMB];
__device__ float g_zinf[NUx];
__device__ float g_zint[NUx];
__device__ float g_gate[264];
__device__ float g_sums[4];
__device__ int g_degU[NUx];
__device__ int g_degI[NIx];
__device__ int g_degT[NUx];
__device__ int g_curU[NUx];
__device__ int g_curI[NIx];
__device__ int g_curT[NUx];
__device__ int g_bsumU[64];
__device__ int g_bsumI[64];
__device__ int g_bsumT[64];
__device__ int g_off_item[NIx + 1];
__device__ int g_off_urate[NUx + 1];
__device__ int g_off_trust[NUx + 1];
__device__ int g_val_item[ERx];
__device__ int g_val_urate[ERx];
__device__ int g_val_trust[ETx];

// ---------------- job descriptors ----------------
struct GJob { const float* W; const float* B; void* Y; int half; };
struct GJobs { GJob j[4]; int m; };

struct GatJob {
    const int* off; const int* val; const __half* fs; const float* fd;
    const float* attn; const float* bias; const void* resid; int rstride;
    void* out; int ostride; int n; int outhalf;
};
struct GatJobs { GatJob j[3]; int n0, n01, ntot; };

static __device__ __forceinline__ unsigned smem_u32(const void* p) {
    return (unsigned)__cvta_generic_to_shared(p);
}

// ---------------- kernels ----------------

// copy eu->hu_all[:,0:64], ei->hi_all[:,0:64] (fp32 -> fp16)
__global__ void copy_all(const float* __restrict__ eu, const float* __restrict__ ei,
                         __half* __restrict__ hu, __half* __restrict__ hi) {
    int i = blockIdx.x * blockDim.x + threadIdx.x;
    if (i < NUx * 64) {
        int row = i >> 6, j = i & 63;
        hu[(size_t)row * HALL + j] = __float2half(eu[i]);
    } else {
        int k = i - NUx * 64;
        if (k >= NIx * 64) return;
        int row = k >> 6, j = k & 63;
        hi[(size_t)row * HALL + j] = __float2half(ei[k]);
    }
}

// ---- CSR build (fused) ----
__global__ void zero3(int* __restrict__ a, int na, int* __restrict__ b, int nb_,
                      int* __restrict__ c, int nc) {
    int i = blockIdx.x * blockDim.x + threadIdx.x;
    if (i < na) a[i] = 0;
    else if (i < na + nb_) b[i - na] = 0;
    else if (i < na + nb_ + nc) c[i - na - nb_] = 0;
}

__global__ void count_all(const int* __restrict__ rsrc, const int* __restrict__ rdst,
                          const int* __restrict__ tdst,
                          int* __restrict__ degU, int* __restrict__ degI,
                          int* __restrict__ degT) {
    int e = blockIdx.x * blockDim.x + threadIdx.x;
    if (e < ERx) {
        atomicAdd(degU + rsrc[e], 1);
        atomicAdd(degI + rdst[e], 1);
    } else {
        int t = e - ERx;
        if (t < ETx) atomicAdd(degT + tdst[t], 1);
    }
}

__global__ void scan_bsums_all(const int* __restrict__ degU, const int* __restrict__ degI,
                               const int* __restrict__ degT,
                               int* __restrict__ bsumU, int* __restrict__ bsumI,
                               int* __restrict__ bsumT) {
    __shared__ int sh[256];
    int t = threadIdx.x;
    const int* deg; int n; int* bsum; int blk;
    if (blockIdx.x < NBU)            { deg = degU; n = NUx; bsum = bsumU; blk = blockIdx.x; }
    else if (blockIdx.x < NBU + NBI) { deg = degI; n = NIx; bsum = bsumI; blk = blockIdx.x - NBU; }
    else                             { deg = degT; n = NUx; bsum = bsumT; blk = blockIdx.x - NBU - NBI; }
    int base = blk * 4096;
    int s = 0;
#pragma unroll
    for (int i = 0; i < 16; i++) {
        int idx = base + i * 256 + t;
        if (idx < n) s += deg[idx];
    }
    sh[t] = s;
    __syncthreads();
    for (int st = 128; st; st >>= 1) {
        if (t < st) sh[t] += sh[t + st];
        __syncthreads();
    }
    if (t == 0) bsum[blk] = sh[0];
}

__global__ void scan_tops_all(int* __restrict__ bsumU, int* __restrict__ bsumI,
                              int* __restrict__ bsumT,
                              int* __restrict__ offU, int* __restrict__ offI,
                              int* __restrict__ offT) {
    __shared__ int sh[64];
    int t = threadIdx.x;
    int* bsum; int nb; int* total;
    if (blockIdx.x == 0)      { bsum = bsumU; nb = NBU; total = offU + NUx; }
    else if (blockIdx.x == 1) { bsum = bsumI; nb = NBI; total = offI + NIx; }
    else                      { bsum = bsumT; nb = NBU; total = offT + NUx; }
    int v = (t < nb) ? bsum[t] : 0;
    sh[t] = v;
    __syncthreads();
    for (int st = 1; st < 64; st <<= 1) {
        int x = (t >= st) ? sh[t - st] : 0;
        __syncthreads();
        sh[t] += x;
        __syncthreads();
    }
    if (t < nb) bsum[t] = sh[t] - v;
    if (t == 63) *total = sh[63];
}

__global__ void scan_final_all(const int* __restrict__ degU, const int* __restrict__ degI,
                               const int* __restrict__ degT,
                               const int* __restrict__ bsumU, const int* __restrict__ bsumI,
                               const int* __restrict__ bsumT,
                               int* __restrict__ offU, int* __restrict__ offI,
                               int* __restrict__ offT) {
    __shared__ int sh[256];
    int t = threadIdx.x;
    const int* deg; int n; const int* bsum; int* off; int blk;
    if (blockIdx.x < NBU)            { deg = degU; n = NUx; bsum = bsumU; off = offU; blk = blockIdx.x; }
    else if (blockIdx.x < NBU + NBI) { deg = degI; n = NIx; bsum = bsumI; off = offI; blk = blockIdx.x - NBU; }
    else                             { deg = degT; n = NUx; bsum = bsumT; off = offT; blk = blockIdx.x - NBU - NBI; }
    int base = blk * 4096 + t * 16;
    int local[16];
    int s = 0;
#pragma unroll
    for (int i = 0; i < 16; i++) {
        int idx = base + i;
        int d = (idx < n) ? deg[idx] : 0;
        local[i] = d;
        s += d;
    }
    sh[t] = s;
    __syncthreads();
    int v = s;
    for (int st = 1; st < 256; st <<= 1) {
        int x = (t >= st) ? sh[t - st] : 0;
        __syncthreads();
        sh[t] += x;
        __syncthreads();
    }
    int run = bsum[blk] + sh[t] - v;
#pragma unroll
    for (int i = 0; i < 16; i++) {
        int idx = base + i;
        if (idx < n) off[idx] = run;
        run += local[i];
    }
}

__global__ void scatter_all(const int* __restrict__ rsrc, const int* __restrict__ rdst,
                            const int* __restrict__ tsrc, const int* __restrict__ tdst,
                            const int* __restrict__ offU, const int* __restrict__ offI,
                            const int* __restrict__ offT,
                            int* __restrict__ curU, int* __restrict__ curI,
                            int* __restrict__ curT,
                            int* __restrict__ valU, int* __restrict__ valI,
                            int* __restrict__ valT) {
    int e = blockIdx.x * blockDim.x + threadIdx.x;
    if (e < ERx) {
        int s = rsrc[e], d = rdst[e];
        int pI = offI[d] + atomicAdd(curI + d, 1);
        valI[pI] = s;
        int pU = offU[s] + atomicAdd(curU + s, 1);
        valU[pU] = d;
    } else {
        int t = e - ERx;
        if (t >= ETx) return;
        int d = tdst[t];
        int pos = offT[d] + atomicAdd(curT + d, 1);
        valT[pos] = tsrc[t];
    }
}

// ---- merged U+I batched GEMM via fp16 tensor cores, X already fp16 ----
__global__ void gemm64_tc2(const __half* __restrict__ XU, int nU, int nbUg, GJobs ju,
                           const __half* __restrict__ XI, int nI, GJobs ji) {
    __shared__ __half sX[64 * 72];
    __shared__ __half sWh[64 * 72];
    __shared__ float sB[64];
    int tx = threadIdx.x;            // 128
    int warp = tx >> 5, lane = tx & 31;

    const __half* X; int n; GJobs jobs; int row0;
    if ((int)blockIdx.x < nbUg) { X = XU; n = nU; jobs = ju; row0 = blockIdx.x * 64; }
    else                        { X = XI; n = nI; jobs = ji; row0 = (blockIdx.x - nbUg) * 64; }

    {
        int r = tx & 63, qu = tx >> 6;   // qu 0..1 -> cols 32qu..32qu+31
        int row = row0 + r;
        if (row < n) {
            const uint2* xr = (const uint2*)(X + (size_t)row * HALL) + qu * 8;
#pragma unroll
            for (int j = 0; j < 8; j++)
                *(uint2*)&sX[r * 72 + qu * 32 + j * 4] = xr[j];
        } else {
#pragma unroll
            for (int j = 0; j < 8; j++)
                *(uint2*)&sX[r * 72 + qu * 32 + j * 4] = make_uint2(0u, 0u);
        }
    }

    int m0 = warp * 16;
    int g = lane >> 2;
    int c2 = (lane & 3) * 2;

    for (int m = 0; m < jobs.m; m++) {
        const float* Wm; const float* Bm; void* Ym; int halfm;
        switch (m) {
            case 0: Wm = jobs.j[0].W; Bm = jobs.j[0].B; Ym = jobs.j[0].Y; halfm = jobs.j[0].half; break;
            case 1: Wm = jobs.j[1].W; Bm = jobs.j[1].B; Ym = jobs.j[1].Y; halfm = jobs.j[1].half; break;
            case 2: Wm = jobs.j[2].W; Bm = jobs.j[2].B; Ym = jobs.j[2].Y; halfm = jobs.j[2].half; break;
            default: Wm = jobs.j[3].W; Bm = jobs.j[3].B; Ym = jobs.j[3].Y; halfm = jobs.j[3].half; break;
        }
        __syncthreads();
        for (int i = tx; i < 1024; i += 128) {
            float4 w = ((const float4*)Wm)[i];
            __half2 h0 = __floats2half2_rn(w.x, w.y);
            __half2 h1 = __floats2half2_rn(w.z, w.w);
            int r = i >> 4, c4 = (i & 15) * 4;
            *(uint2*)&sWh[r * 72 + c4] = make_uint2(*(unsigned*)&h0, *(unsigned*)&h1);
        }
        if (tx < 64) sB[tx] = Bm[tx];
        __syncthreads();

        float acc[8][4];
#pragma unroll
        for (int nt = 0; nt < 8; nt++)
#pragma unroll
            for (int q = 0; q < 4; q++) acc[nt][q] = 0.f;

#pragma unroll
        for (int kc = 0; kc < 4; kc++) {
            unsigned a0, a1, a2, a3;
            {
                int l8 = lane & 7;
                int rsel = (lane & 8) ? 8 : 0;
                int csel = (lane & 16) ? 8 : 0;
                unsigned aaddr = smem_u32(&sX[(m0 + l8 + rsel) * 72 + kc * 16 + csel]);
                asm volatile("ldmatrix.sync.aligned.m8n8.x4.shared.b16 {%0,%1,%2,%3}, [%4];"
                             : "=r"(a0), "=r"(a1), "=r"(a2), "=r"(a3) : "r"(aaddr));
            }
#pragma unroll
            for (int nt = 0; nt < 8; nt++) {
                unsigned b0, b1;
                int krow = kc * 16 + (lane & 15);
                unsigned baddr = smem_u32(&sWh[krow * 72 + nt * 8]);
                asm volatile("ldmatrix.sync.aligned.m8n8.x2.trans.shared.b16 {%0,%1}, [%2];"
                             : "=r"(b0), "=r"(b1) : "r"(baddr));
                asm volatile("mma.sync.aligned.m16n8k16.row.col.f32.f16.f16.f32 "
                             "{%0,%1,%2,%3}, {%4,%5,%6,%7}, {%8,%9}, {%0,%1,%2,%3};"
                             : "+f"(acc[nt][0]), "+f"(acc[nt][1]),
                               "+f"(acc[nt][2]), "+f"(acc[nt][3])
                             : "r"(a0), "r"(a1), "r"(a2), "r"(a3), "r"(b0), "r"(b1));
            }
        }

        int r1 = row0 + m0 + g;
        int r2 = r1 + 8;
#pragma unroll
        for (int nt = 0; nt < 8; nt++) {
            float bv0 = sB[nt * 8 + c2];
            float bv1 = sB[nt * 8 + c2 + 1];
            float v00 = acc[nt][0] + bv0, v01 = acc[nt][1] + bv1;
            float v10 = acc[nt][2] + bv0, v11 = acc[nt][3] + bv1;
            if (halfm) {
                __half* yh = (__half*)Ym;
                if (r1 < n) {
                    __half2 h = __floats2half2_rn(v00, v01);
                    *(__half2*)(yh + (size_t)r1 * 64 + nt * 8 + c2) = h;
                }
                if (r2 < n) {
                    __half2 h = __floats2half2_rn(v10, v11);
                    *(__half2*)(yh + (size_t)r2 * 64 + nt * 8 + c2) = h;
                }
            } else {
                float* yf = (float*)Ym;
                if (r1 < n) *(float2*)(yf + (size_t)r1 * 64 + nt * 8 + c2) = make_float2(v00, v01);
                if (r2 < n) *(float2*)(yf + (size_t)r2 * 64 + nt * 8 + c2) = make_float2(v10, v11);
            }
        }
    }
}

// ---- merged GAT gather: warp per dst node, half-warp per edge, fp16 fs rows ----
__global__ void gat_gather3(GatJobs jobs) {
    int w = (blockIdx.x * blockDim.x + threadIdx.x) >> 5;
    int lane = threadIdx.x & 31;
    if (w >= jobs.ntot) return;
    GatJob jb;
    int node;
    if (w < jobs.n0)        { jb = jobs.j[0]; node = w; }
    else if (w < jobs.n01)  { jb = jobs.j[1]; node = w - jobs.n0; }
    else                    { jb = jobs.j[2]; node = w - jobs.n01; }

    int h = lane & 15;
    int half = lane >> 4;
    float4 fdv = ((const float4*)(jb.fd + (size_t)node * 64))[h];
    float4 at  = ((const float4*)jb.attn)[h];
    int b = jb.off[node], e = jb.off[node + 1];
    const __half* fs = jb.fs;
    const int* val = jb.val;

    float denom = 0.f;
    float4 acc = make_float4(0.f, 0.f, 0.f, 0.f);
    int nit = (e - b + 1) >> 1;
    int basej = b + half;

    uint2 A0r = make_uint2(0, 0);
    uint2 A1r = A0r;
    if (nit > 0)
        A0r = ((const uint2*)(fs + (size_t)val[min(basej, e - 1)] * 64))[h];
    if (nit > 1)
        A1r = ((const uint2*)(fs + (size_t)val[min(basej + 2, e - 1)] * 64))[h];

    for (int it = 0; it < nit; it++) {
        uint2 Ar = A0r;
        A0r = A1r;
        if (it + 2 < nit)
            A1r = ((const uint2*)(fs + (size_t)val[min(basej + 2 * (it + 2), e - 1)] * 64))[h];
        __half2* ah = (__half2*)&Ar;
        float2 a01 = __half22float2(ah[0]);
        float2 a23 = __half22float2(ah[1]);
        int j = basej + 2 * it;
        float x0 = a01.x + fdv.x, x1 = a01.y + fdv.y;
        float x2 = a23.x + fdv.z, x3 = a23.y + fdv.w;
        x0 = x0 > 0.f ? x0 : 0.2f * x0;
        x1 = x1 > 0.f ? x1 : 0.2f * x1;
        x2 = x2 > 0.f ? x2 : 0.2f * x2;
        x3 = x3 > 0.f ? x3 : 0.2f * x3;
        float p = x0 * at.x + x1 * at.y + x2 * at.z + x3 * at.w;
#pragma unroll
        for (int o = 8; o; o >>= 1) p += __shfl_xor_sync(0xffffffffu, p, o);
        float ex = (j < e) ? __expf(p) : 0.f;
        denom += ex;
        acc.x += ex * a01.x;
        acc.y += ex * a01.y;
        acc.z += ex * a23.x;
        acc.w += ex * a23.y;
    }
    denom += __shfl_xor_sync(0xffffffffu, denom, 16);
    acc.x += __shfl_xor_sync(0xffffffffu, acc.x, 16);
    acc.y += __shfl_xor_sync(0xffffffffu, acc.y, 16);
    acc.z += __shfl_xor_sync(0xffffffffu, acc.z, 16);
    acc.w += __shfl_xor_sync(0xffffffffu, acc.w, 16);

    if (half == 0) {
        float inv = denom > 0.f ? 1.0f / denom : 0.f;
        float4 bv = ((const float4*)jb.bias)[h];
        float v0 = acc.x * inv + bv.x;
        float v1 = acc.y * inv + bv.y;
        float v2 = acc.z * inv + bv.z;
        float v3 = acc.w * inv + bv.w;
        if (jb.outhalf) {
            if (jb.resid) {
                const __half2* rp = (const __half2*)((const __half*)jb.resid +
                                                     (size_t)node * jb.rstride);
                float2 r01 = __half22float2(rp[2 * h]);
                float2 r23 = __half22float2(rp[2 * h + 1]);
                v0 += r01.x; v1 += r01.y; v2 += r23.x; v3 += r23.y;
            }
            __half2* op = (__half2*)((__half*)jb.out + (size_t)node * jb.ostride);
            op[2 * h]     = __floats2half2_rn(v0, v1);
            op[2 * h + 1] = __floats2half2_rn(v2, v3);
        } else {
            float4* op = (float4*)((float*)jb.out + (size_t)node * jb.ostride);
            *(op + h) = make_float4(v0, v1, v2, v3);
        }
    }
}

// collapse gate MLP + zero the BN sums for this layer
__global__ void gate_prep(const float* __restrict__ W1, const float* __restrict__ b1,
                          const float* __restrict__ W2, const float* __restrict__ b2,
                          float* __restrict__ gout, float* __restrict__ sums) {
    int t = threadIdx.x;          // 256
    if (t < 4) sums[t] = 0.f;
    int i = t >> 7, k = t & 127;
    const float* w1 = W1 + (size_t)i * 128 * 128 + (size_t)k * 128;
    const float* w2 = W2 + i * 128;
    float v = 0.f;
    for (int j = 0; j < 128; j++) v += w1[j] * w2[j];
    gout[i * 132 + k] = v;
    if (k == 0) {
        float c = b2[i];
        const float* bb = b1 + i * 128;
        for (int j = 0; j < 128; j++) c += bb[j] * w2[j];
        gout[i * 132 + 128] = c;
    }
}

__global__ void z_kernel(const __half* __restrict__ HU, const float* __restrict__ p,
                         const float* __restrict__ q, const float* __restrict__ gate,
                         float* __restrict__ zinf, float* __restrict__ zint,
                         float* __restrict__ sums, int n) {
    __shared__ float red[8][4];
    int w = (blockIdx.x * blockDim.x + threadIdx.x) >> 5;
    int wl = threadIdx.x >> 5;
    int lane = threadIdx.x & 31;
    float zi = 0.f, zt = 0.f;
    if (w < n) {
        float2 h = __half22float2(((const __half2*)(HU + (size_t)w * HALL))[lane]);
        float2 pv = ((const float2*)(p  + (size_t)w * 64))[lane];
        float2 qv = ((const float2*)(q  + (size_t)w * 64))[lane];
        const float2* vinf = (const float2*)gate;
        const float2* vint = (const float2*)(gate + 132);
        float2 vi0 = vinf[lane], vi1 = vinf[32 + lane];
        float2 vt0 = vint[lane], vt1 = vint[32 + lane];
        zi = h.x * vi0.x + h.y * vi0.y + pv.x * vi1.x + pv.y * vi1.y;
        zt = h.x * vt0.x + h.y * vt0.y + qv.x * vt1.x + qv.y * vt1.y;
    }
#pragma unroll
    for (int off = 16; off; off >>= 1) {
        zi += __shfl_down_sync(0xffffffffu, zi, off);
        zt += __shfl_down_sync(0xffffffffu, zt, off);
    }
    if (lane == 0) {
        if (w < n) {
            zi += gate[128]; zt += gate[132 + 128];
            zinf[w] = zi; zint[w] = zt;
            red[wl][0] = zi; red[wl][1] = zi * zi;
            red[wl][2] = zt; red[wl][3] = zt * zt;
        } else {
            red[wl][0] = red[wl][1] = red[wl][2] = red[wl][3] = 0.f;
        }
    }
    __syncthreads();
    if (threadIdx.x < 4) {
        float s = 0.f;
        for (int k = 0; k < 8; k++) s += red[k][threadIdx.x];
        atomicAdd(sums + threadIdx.x, s);
    }
}

__global__ void gate_apply(const __half* __restrict__ HU, __half* __restrict__ HUo,
                           const float* __restrict__ p, const float* __restrict__ q,
                           const float* __restrict__ zinf, const float* __restrict__ zint,
                           const float* __restrict__ sums, int n) {
    int w = (blockIdx.x * blockDim.x + threadIdx.x) >> 5;
    int lane = threadIdx.x & 31;
    if (w >= n) return;
    float inv = 1.0f / (float)n;
    float mu0 = sums[0] * inv;
    float var0 = sums[1] * inv - mu0 * mu0;
    float mu1 = sums[2] * inv;
    float var1 = sums[3] * inv - mu1 * mu1;
    float a0 = (zinf[w] - mu0) * rsqrtf(var0 + 1e-5f);
    float a1 = (zint[w] - mu1) * rsqrtf(var1 + 1e-5f);
    a0 = a0 > 0.f ? a0 : 0.01f * a0;
    a1 = a1 > 0.f ? a1 : 0.01f * a1;
    float m = fmaxf(a0, a1);
    float e0 = __expf(a0 - m), e1 = __expf(a1 - m);
    float g0 = e0 / (e0 + e1), g1 = e1 / (e0 + e1);
    float2 pv = ((const float2*)(p + (size_t)w * 64))[lane];
    float2 qv = ((const float2*)(q + (size_t)w * 64))[lane];
    float2 hv = __half22float2(((const __half2*)(HU + (size_t)w * HALL))[lane]);
    float ox = g0 * pv.x + g1 * qv.x + hv.x;
    float oy = g0 * pv.y + g1 * qv.y + hv.y;
    ((__half2*)(HUo + (size_t)w * HALL))[lane] = __floats2half2_rn(ox, oy);
}

// both pos and neg pairs in one launch (fp16 rows, fp32 accumulate)
__global__ void pair2_kernel(const int* __restrict__ pu, const int* __restrict__ pi,
                             const int* __restrict__ nu, const int* __restrict__ ni,
                             const __half* __restrict__ hu_all,
                             const __half* __restrict__ hi_all,
                             float* __restrict__ out) {
    int w = (blockIdx.x * blockDim.x + threadIdx.x) >> 5;
    int lane = threadIdx.x & 31;
    if (w >= 2 * EPx) return;
    const int* uu = (w < EPx) ? pu : nu;
    const int* ii = (w < EPx) ? pi : ni;
    int idx = (w < EPx) ? w : w - EPx;
    const __half2* hr = (const __half2*)(hu_all + (size_t)uu[idx] * HALL);
    const __half2* ir = (const __half2*)(hi_all + (size_t)ii[idx] * HALL);
    float s = 0.f;
#pragma unroll
    for (int c = 0; c < 3; c++) {
        float2 a = __half22float2(hr[lane + 32 * c]);
        float2 b = __half22float2(ir[lane + 32 * c]);
        s += a.x * b.x + a.y * b.y;
    }
#pragma unroll
    for (int off = 16; off; off >>= 1) s += __shfl_down_sync(0xffffffffu, s, off);
    if (lane == 0) out[w] = s;
}

// ---------------- host ----------------

static void* sym_addr(const void* s) {
    void* p = nullptr;
    cudaGetSymbolAddress(&p, s);
    return p;
}

extern "C" void kernel_launch(void* const* d_in, const int* in_sizes, int n_in,
                              void* d_out, int out_size) {
    int wf = -1, gf = -1;
    for (int i = 0; i < n_in; i++) {
        if (wf < 0 && in_sizes[i] == NUx * EMB) wf = i;   // eu
        if (gf < 0 && in_sizes[i] == ERx) gf = i;         // rate_src
    }
    if (wf < 0) wf = 0;
    if (gf < 0) gf = (wf == 0) ? 18 : 0;
    const float* eu        = (const float*)d_in[wf + 0];
    const float* ei        = (const float*)d_in[wf + 1];
    const float* rate_W    = (const float*)d_in[wf + 2];
    const float* rate_b    = (const float*)d_in[wf + 3];
    const float* rate_attn = (const float*)d_in[wf + 4];
    const float* rate_bias = (const float*)d_in[wf + 5];
    const float* rb_W      = (const float*)d_in[wf + 6];
    const float* rb_b      = (const float*)d_in[wf + 7];
    const float* rb_attn   = (const float*)d_in[wf + 8];
    const float* rb_bias   = (const float*)d_in[wf + 9];
    const float* tr_W      = (const float*)d_in[wf + 10];
    const float* tr_b      = (const float*)d_in[wf + 11];
    const float* tr_attn   = (const float*)d_in[wf + 12];
    const float* tr_bias   = (const float*)d_in[wf + 13];
    const float* attW1     = (const float*)d_in[wf + 14];
    const float* attb1     = (const float*)d_in[wf + 15];
    const float* attW2     = (const float*)d_in[wf + 16];
    const float* attb2     = (const float*)d_in[wf + 17];
    const int* rate_src  = (const int*)d_in[gf + 0];
    const int* rate_dst  = (const int*)d_in[gf + 1];
    const int* trust_src = (const int*)d_in[gf + 2];
    const int* trust_dst = (const int*)d_in[gf + 3];
    const int* pos_u     = (const int*)d_in[gf + 4];
    const int* pos_i     = (const int*)d_in[gf + 5];
    const int* neg_u     = (const int*)d_in[gf + 6];
    const int* neg_i     = (const int*)d_in[gf + 7];

    __half* hu_all = (__half*)sym_addr(g_hu_all);
    __half* hi_all = (__half*)sym_addr(g_hi_all);
    __half* fsU_rate = (__half*)sym_addr(g_fsU_rate);
    __half* fsU_tr   = (__half*)sym_addr(g_fsU_tr);
    __half* fsI_rb   = (__half*)sym_addr(g_fsI_rb);
    float* fdU_rb   = (float*)sym_addr(g_fdU_rb);
    float* fdU_tr   = (float*)sym_addr(g_fdU_tr);
    float* fdI_rate = (float*)sym_addr(g_fdI_rate);
    float* pbuf   = (float*)sym_addr(g_p);
    float* qbuf   = (float*)sym_addr(g_q);
    float* zinf   = (float*)sym_addr(g_zinf);
    float* zint   = (float*)sym_addr(g_zint);
    float* gate   = (float*)sym_addr(g_gate);
    float* sums   = (float*)sym_addr(g_sums);
    int* degU     = (int*)sym_addr(g_degU);
    int* degI     = (int*)sym_addr(g_degI);
    int* degT     = (int*)sym_addr(g_degT);
    int* curU     = (int*)sym_addr(g_curU);
    int* curI     = (int*)sym_addr(g_curI);
    int* curT     = (int*)sym_addr(g_curT);
    int* bsumU    = (int*)sym_addr(g_bsumU);
    int* bsumI    = (int*)sym_addr(g_bsumI);
    int* bsumT    = (int*)sym_addr(g_bsumT);
    int* off_item  = (int*)sym_addr(g_off_item);
    int* off_urate = (int*)sym_addr(g_off_urate);
    int* off_trust = (int*)sym_addr(g_off_trust);
    int* val_item  = (int*)sym_addr(g_val_item);
    int* val_urate = (int*)sym_addr(g_val_urate);
    int* val_trust = (int*)sym_addr(g_val_trust);
    float* out    = (float*)d_out;

    // ---- fused CSR build ----
    int ntotdeg = NUx + NIx + NUx;
    zero3<<<(ntotdeg + 255) / 256, 256>>>(degU, NUx, degI, NIx, degT, NUx);
    count_all<<<(ERx + ETx + 255) / 256, 256>>>(rate_src, rate_dst, trust_dst,
                                                degU, degI, degT);
    scan_bsums_all<<<NBU + NBI + NBU, 256>>>(degU, degI, degT, bsumU, bsumI, bsumT);
    scan_tops_all<<<3, 64>>>(bsumU, bsumI, bsumT, off_urate, off_item, off_trust);
    scan_final_all<<<NBU + NBI + NBU, 256>>>(degU, degI, degT, bsumU, bsumI, bsumT,
                                             off_urate, off_item, off_trust);
    zero3<<<(ntotdeg + 255) / 256, 256>>>(curU, NUx, curI, NIx, curT, NUx);
    scatter_all<<<(ERx + ETx + 255) / 256, 256>>>(rate_src, rate_dst, trust_src, trust_dst,
                                                  off_urate, off_item, off_trust,
                                                  curU, curI, curT,
                                                  val_urate, val_item, val_trust);

    copy_all<<<((NUx + NIx) * 64 + 255) / 256, 256>>>(eu, ei, hu_all, hi_all);

    int nbUg = (NUx + 63) / 64;
    int nbIg = (NIx + 63) / 64;

    for (int l = 0; l < NLAYERS; l++) {
        const __half* HU = hu_all + l * 64;        // stride HALL
        __half* HUo      = hu_all + (l + 1) * 64;
        const __half* HI = hi_all + l * 64;
        __half* HIo      = hi_all + (l + 1) * 64;

        const float* rW = rate_W + (size_t)l * 2 * 4096;
        const float* rB = rate_b + (size_t)l * 2 * 64;
        const float* bW = rb_W   + (size_t)l * 2 * 4096;
        const float* bB = rb_b   + (size_t)l * 2 * 64;
        const float* tW = tr_W   + (size_t)l * 2 * 4096;
        const float* tB = tr_b   + (size_t)l * 2 * 64;

        GJobs ju;
        ju.m = 4;
        ju.j[0] = { rW,        rB,        (void*)fsU_rate, 1 };
        ju.j[1] = { bW + 4096, bB + 64,   (void*)fdU_rb,   0 };
        ju.j[2] = { tW,        tB,        (void*)fsU_tr,   1 };
        ju.j[3] = { tW + 4096, tB + 64,   (void*)fdU_tr,   0 };
        GJobs ji;
        ji.m = 2;
        ji.j[0] = { rW + 4096, rB + 64,   (void*)fdI_rate, 0 };
        ji.j[1] = { bW,        bB,        (void*)fsI_rb,   1 };
        ji.j[2] = { nullptr, nullptr, nullptr, 0 };
        ji.j[3] = { nullptr, nullptr, nullptr, 0 };
        gemm64_tc2<<<nbUg + nbIg, 128>>>(HU, NUx, nbUg, ju, HI, NIx, ji);

        GatJobs gj;
        gj.j[0] = { off_item,  val_item,  fsU_rate, fdI_rate,
                    rate_attn + l * 64, rate_bias + l * 64,
                    (const void*)HI, HALL, (void*)HIo, HALL, NIx, 1 };
        gj.j[1] = { off_urate, val_urate, fsI_rb,   fdU_rb,
                    rb_attn + l * 64,   rb_bias + l * 64,
                    nullptr, 0, (void*)qbuf, 64, NUx, 0 };
        gj.j[2] = { off_trust, val_trust, fsU_tr,   fdU_tr,
                    tr_attn + l * 64,   tr_bias + l * 64,
                    nullptr, 0, (void*)pbuf, 64, NUx, 0 };
        gj.n0 = NIx; gj.n01 = NIx + NUx; gj.ntot = NIx + 2 * NUx;
        gat_gather3<<<(gj.ntot * 32 + 255) / 256, 256>>>(gj);

        gate_prep<<<1, 256>>>(attW1 + (size_t)l * 2 * 128 * 128,
                              attb1 + (size_t)l * 2 * 128,
                              attW2 + (size_t)l * 2 * 128,
                              attb2 + (size_t)l * 2, gate, sums);
        z_kernel<<<(NUx + 7) / 8, 256>>>(HU, pbuf, qbuf, gate, zinf, zint, sums, NUx);
        gate_apply<<<(NUx + 7) / 8, 256>>>(HU, HUo, pbuf, qbuf, zinf, zint, sums, NUx);
    }

    pair2_kernel<<<(2 * EPx + 7) / 8, 256>>>(pos_u, pos_i, neg_u, neg_i,
                                             hu_all, hi_all, out);
}

// round 16
// speedup vs baseline: 1.3633x; 1.3633x over previous
#include <cuda_runtime.h>
#include <cuda_fp16.h>
#include <math.h>

#define EMB 64
#define NLAYERS 2
#define NUx 100000
#define NIx 50000
#define ERx 1000000
#define ETx 800000
#define EPx 200000
#define HALL 192   // EMB*(1+L)
#define NBU 25     // ceil(NUx/4096)
#define NBI 13     // ceil(NIx/4096)

// ---------------- static scratch (no allocations allowed) ----------------
__device__ float g_hu_all[(size_t)NUx * HALL];
__device__ float g_hi_all[(size_t)NIx * HALL];
__device__ __half g_hu_h[(size_t)NUx * HALL];
__device__ __half g_hi_h[(size_t)NIx * HALL];
__device__ __half g_fsU_rate[(size_t)NUx * EMB];
__device__ __half g_fsU_tr[(size_t)NUx * EMB];
__device__ __half g_fsI_rb[(size_t)NIx * EMB];
__device__ float g_fdU_rb[(size_t)NUx * EMB];
__device__ float g_fdU_tr[(size_t)NUx * EMB];
__device__ float g_fdI_rate[(size_t)NIx * EMB];
__device__ float g_p[(size_t)NUx * EMB];
__device__ float g_q[(size_t)NUx * EMB];
__device__ float g_zinf[NUx];
__device__ float g_zint[NUx];
__device__ float g_gate[264];
__device__ float g_sums[4];
__device__ int g_degU[NUx];
__device__ int g_degI[NIx];
__device__ int g_degT[NUx];
__device__ int g_curU[NUx];
__device__ int g_curI[NIx];
__device__ int g_curT[NUx];
__device__ int g_bsumU[64];
__device__ int g_bsumI[64];
__device__ int g_bsumT[64];
__device__ int g_off_item[NIx + 1];
__device__ int g_off_urate[NUx + 1];
__device__ int g_off_trust[NUx + 1];
__device__ int g_val_item[ERx];
__device__ int g_val_urate[ERx];
__device__ int g_val_trust[ETx];

// ---------------- job descriptors ----------------
struct GJob { const float* W; const float* B; void* Y; int half; };
struct GJobs { GJob j[4]; int m; };

struct GatJob {
    const int* off; const int* val; const __half* fs; const float* fd;
    const float* attn; const float* bias; const float* resid; int rstride;
    float* out; int ostride; int n;
};
struct GatJobs { GatJob j[3]; int n0, n01, ntot; };

static __device__ __forceinline__ unsigned smem_u32(const void* p) {
    return (unsigned)__cvta_generic_to_shared(p);
}

// ---------------- kernels ----------------

// copy eu->hu_all[:,0:64] and ei->hi_all[:,0:64] in one launch
__global__ void copy_all(const float* __restrict__ eu, const float* __restrict__ ei,
                         float* __restrict__ hu, float* __restrict__ hi) {
    int i = blockIdx.x * blockDim.x + threadIdx.x;
    if (i < NUx * 64) {
        int row = i >> 6, j = i & 63;
        hu[(size_t)row * HALL + j] = eu[i];
    } else {
        int k = i - NUx * 64;
        if (k >= NIx * 64) return;
        int row = k >> 6, j = k & 63;
        hi[(size_t)row * HALL + j] = ei[k];
    }
}

// convert hu_all/hi_all to fp16 pair tables (after layer loop), float2->half2
__global__ void tohalf_pair(const float* __restrict__ hu, const float* __restrict__ hi,
                            __half* __restrict__ huh, __half* __restrict__ hih) {
    int i = blockIdx.x * blockDim.x + threadIdx.x;   // in float2 units
    int nU2 = NUx * HALL / 2;
    int nI2 = NIx * HALL / 2;
    if (i < nU2) {
        float2 v = ((const float2*)hu)[i];
        ((__half2*)huh)[i] = __floats2half2_rn(v.x, v.y);
    } else {
        int k = i - nU2;
        if (k >= nI2) return;
        float2 v = ((const float2*)hi)[k];
        ((__half2*)hih)[k] = __floats2half2_rn(v.x, v.y);
    }
}

// ---- CSR build (fused) ----
__global__ void zero3(int* __restrict__ a, int na, int* __restrict__ b, int nb_,
                      int* __restrict__ c, int nc) {
    int i = blockIdx.x * blockDim.x + threadIdx.x;
    if (i < na) a[i] = 0;
    else if (i < na + nb_) b[i - na] = 0;
    else if (i < na + nb_ + nc) c[i - na - nb_] = 0;
}

__global__ void count_all(const int* __restrict__ rsrc, const int* __restrict__ rdst,
                          const int* __restrict__ tdst,
                          int* __restrict__ degU, int* __restrict__ degI,
                          int* __restrict__ degT) {
    int e = blockIdx.x * blockDim.x + threadIdx.x;
    if (e < ERx) {
        atomicAdd(degU + rsrc[e], 1);
        atomicAdd(degI + rdst[e], 1);
    } else {
        int t = e - ERx;
        if (t < ETx) atomicAdd(degT + tdst[t], 1);
    }
}

__global__ void scan_bsums_all(const int* __restrict__ degU, const int* __restrict__ degI,
                               const int* __restrict__ degT,
                               int* __restrict__ bsumU, int* __restrict__ bsumI,
                               int* __restrict__ bsumT) {
    __shared__ int sh[256];
    int t = threadIdx.x;
    const int* deg; int n; int* bsum; int blk;
    if (blockIdx.x < NBU)            { deg = degU; n = NUx; bsum = bsumU; blk = blockIdx.x; }
    else if (blockIdx.x < NBU + NBI) { deg = degI; n = NIx; bsum = bsumI; blk = blockIdx.x - NBU; }
    else                             { deg = degT; n = NUx; bsum = bsumT; blk = blockIdx.x - NBU - NBI; }
    int base = blk * 4096;
    int s = 0;
#pragma unroll
    for (int i = 0; i < 16; i++) {
        int idx = base + i * 256 + t;
        if (idx < n) s += deg[idx];
    }
    sh[t] = s;
    __syncthreads();
    for (int st = 128; st; st >>= 1) {
        if (t < st) sh[t] += sh[t + st];
        __syncthreads();
    }
    if (t == 0) bsum[blk] = sh[0];
}

__global__ void scan_tops_all(int* __restrict__ bsumU, int* __restrict__ bsumI,
                              int* __restrict__ bsumT,
                              int* __restrict__ offU, int* __restrict__ offI,
                              int* __restrict__ offT) {
    __shared__ int sh[64];
    int t = threadIdx.x;
    int* bsum; int nb; int* total;
    if (blockIdx.x == 0)      { bsum = bsumU; nb = NBU; total = offU + NUx; }
    else if (blockIdx.x == 1) { bsum = bsumI; nb = NBI; total = offI + NIx; }
    else                      { bsum = bsumT; nb = NBU; total = offT + NUx; }
    int v = (t < nb) ? bsum[t] : 0;
    sh[t] = v;
    __syncthreads();
    for (int st = 1; st < 64; st <<= 1) {
        int x = (t >= st) ? sh[t - st] : 0;
        __syncthreads();
        sh[t] += x;
        __syncthreads();
    }
    if (t < nb) bsum[t] = sh[t] - v;
    if (t == 63) *total = sh[63];
}

__global__ void scan_final_all(const int* __restrict__ degU, const int* __restrict__ degI,
                               const int* __restrict__ degT,
                               const int* __restrict__ bsumU, const int* __restrict__ bsumI,
                               const int* __restrict__ bsumT,
                               int* __restrict__ offU, int* __restrict__ offI,
                               int* __restrict__ offT) {
    __shared__ int sh[256];
    int t = threadIdx.x;
    const int* deg; int n; const int* bsum; int* off; int blk;
    if (blockIdx.x < NBU)            { deg = degU; n = NUx; bsum = bsumU; off = offU; blk = blockIdx.x; }
    else if (blockIdx.x < NBU + NBI) { deg = degI; n = NIx; bsum = bsumI; off = offI; blk = blockIdx.x - NBU; }
    else                             { deg = degT; n = NUx; bsum = bsumT; off = offT; blk = blockIdx.x - NBU - NBI; }
    int base = blk * 4096 + t * 16;
    int local[16];
    int s = 0;
#pragma unroll
    for (int i = 0; i < 16; i++) {
        int idx = base + i;
        int d = (idx < n) ? deg[idx] : 0;
        local[i] = d;
        s += d;
    }
    sh[t] = s;
    __syncthreads();
    int v = s;
    for (int st = 1; st < 256; st <<= 1) {
        int x = (t >= st) ? sh[t - st] : 0;
        __syncthreads();
        sh[t] += x;
        __syncthreads();
    }
    int run = bsum[blk] + sh[t] - v;
#pragma unroll
    for (int i = 0; i < 16; i++) {
        int idx = base + i;
        if (idx < n) off[idx] = run;
        run += local[i];
    }
}

__global__ void scatter_all(const int* __restrict__ rsrc, const int* __restrict__ rdst,
                            const int* __restrict__ tsrc, const int* __restrict__ tdst,
                            const int* __restrict__ offU, const int* __restrict__ offI,
                            const int* __restrict__ offT,
                            int* __restrict__ curU, int* __restrict__ curI,
                            int* __restrict__ curT,
                            int* __restrict__ valU, int* __restrict__ valI,
                            int* __restrict__ valT) {
    int e = blockIdx.x * blockDim.x + threadIdx.x;
    if (e < ERx) {
        int s = rsrc[e], d = rdst[e];
        int pI = offI[d] + atomicAdd(curI + d, 1);
        valI[pI] = s;
        int pU = offU[s] + atomicAdd(curU + s, 1);
        valU[pU] = d;
    } else {
        int t = e - ERx;
        if (t >= ETx) return;
        int d = tdst[t];
        int pos = offT[d] + atomicAdd(curT + d, 1);
        valT[pos] = tsrc[t];
    }
}

// ---- merged U+I batched GEMM via fp16 tensor cores ----
__global__ void gemm64_tc2(const float* __restrict__ XU, int nU, int nbUg, GJobs ju,
                           const float* __restrict__ XI, int nI, GJobs ji) {
    __shared__ __half sX[64 * 72];
    __shared__ __half sWh[64 * 72];
    __shared__ float sB[64];
    int tx = threadIdx.x;            // 128
    int warp = tx >> 5, lane = tx & 31;

    const float* X; int n; GJobs jobs; int row0;
    if ((int)blockIdx.x < nbUg) { X = XU; n = nU; jobs = ju; row0 = blockIdx.x * 64; }
    else                        { X = XI; n = nI; jobs = ji; row0 = (blockIdx.x - nbUg) * 64; }

    {
        int r = tx & 63, qu = tx >> 6;
        int row = row0 + r;
        if (row < n) {
            const float4* xr = (const float4*)(X + (size_t)row * HALL) + qu * 8;
#pragma unroll
            for (int j = 0; j < 8; j++) {
                float4 v = xr[j];
                __half2 h0 = __floats2half2_rn(v.x, v.y);
                __half2 h1 = __floats2half2_rn(v.z, v.w);
                *(uint2*)&sX[r * 72 + qu * 32 + j * 4] =
                    make_uint2(*(unsigned*)&h0, *(unsigned*)&h1);
            }
        } else {
#pragma unroll
            for (int j = 0; j < 8; j++)
                *(uint2*)&sX[r * 72 + qu * 32 + j * 4] = make_uint2(0u, 0u);
        }
    }

    int m0 = warp * 16;
    int g = lane >> 2;
    int c2 = (lane & 3) * 2;

    for (int m = 0; m < jobs.m; m++) {
        const float* Wm; const float* Bm; void* Ym; int halfm;
        switch (m) {
            case 0: Wm = jobs.j[0].W; Bm = jobs.j[0].B; Ym = jobs.j[0].Y; halfm = jobs.j[0].half; break;
            case 1: Wm = jobs.j[1].W; Bm = jobs.j[1].B; Ym = jobs.j[1].Y; halfm = jobs.j[1].half; break;
            case 2: Wm = jobs.j[2].W; Bm = jobs.j[2].B; Ym = jobs.j[2].Y; halfm = jobs.j[2].half; break;
            default: Wm = jobs.j[3].W; Bm = jobs.j[3].B; Ym = jobs.j[3].Y; halfm = jobs.j[3].half; break;
        }
        __syncthreads();
        for (int i = tx; i < 1024; i += 128) {
            float4 w = ((const float4*)Wm)[i];
            __half2 h0 = __floats2half2_rn(w.x, w.y);
            __half2 h1 = __floats2half2_rn(w.z, w.w);
            int r = i >> 4, c4 = (i & 15) * 4;
            *(uint2*)&sWh[r * 72 + c4] = make_uint2(*(unsigned*)&h0, *(unsigned*)&h1);
        }
        if (tx < 64) sB[tx] = Bm[tx];
        __syncthreads();

        float acc[8][4];
#pragma unroll
        for (int nt = 0; nt < 8; nt++)
#pragma unroll
            for (int q = 0; q < 4; q++) acc[nt][q] = 0.f;

#pragma unroll
        for (int kc = 0; kc < 4; kc++) {
            unsigned a0, a1, a2, a3;
            {
                int l8 = lane & 7;
                int rsel = (lane & 8) ? 8 : 0;
                int csel = (lane & 16) ? 8 : 0;
                unsigned aaddr = smem_u32(&sX[(m0 + l8 + rsel) * 72 + kc * 16 + csel]);
                asm volatile("ldmatrix.sync.aligned.m8n8.x4.shared.b16 {%0,%1,%2,%3}, [%4];"
                             : "=r"(a0), "=r"(a1), "=r"(a2), "=r"(a3) : "r"(aaddr));
            }
#pragma unroll
            for (int nt = 0; nt < 8; nt++) {
                unsigned b0, b1;
                int krow = kc * 16 + (lane & 15);
                unsigned baddr = smem_u32(&sWh[krow * 72 + nt * 8]);
                asm volatile("ldmatrix.sync.aligned.m8n8.x2.trans.shared.b16 {%0,%1}, [%2];"
                             : "=r"(b0), "=r"(b1) : "r"(baddr));
                asm volatile("mma.sync.aligned.m16n8k16.row.col.f32.f16.f16.f32 "
                             "{%0,%1,%2,%3}, {%4,%5,%6,%7}, {%8,%9}, {%0,%1,%2,%3};"
                             : "+f"(acc[nt][0]), "+f"(acc[nt][1]),
                               "+f"(acc[nt][2]), "+f"(acc[nt][3])
                             : "r"(a0), "r"(a1), "r"(a2), "r"(a3), "r"(b0), "r"(b1));
            }
        }

        int r1 = row0 + m0 + g;
        int r2 = r1 + 8;
#pragma unroll
        for (int nt = 0; nt < 8; nt++) {
            float bv0 = sB[nt * 8 + c2];
            float bv1 = sB[nt * 8 + c2 + 1];
            float v00 = acc[nt][0] + bv0, v01 = acc[nt][1] + bv1;
            float v10 = acc[nt][2] + bv0, v11 = acc[nt][3] + bv1;
            if (halfm) {
                __half* yh = (__half*)Ym;
                if (r1 < n) {
                    __half2 h = __floats2half2_rn(v00, v01);
                    *(__half2*)(yh + (size_t)r1 * 64 + nt * 8 + c2) = h;
                }
                if (r2 < n) {
                    __half2 h = __floats2half2_rn(v10, v11);
                    *(__half2*)(yh + (size_t)r2 * 64 + nt * 8 + c2) = h;
                }
            } else {
                float* yf = (float*)Ym;
                if (r1 < n) *(float2*)(yf + (size_t)r1 * 64 + nt * 8 + c2) = make_float2(v00, v01);
                if (r2 < n) *(float2*)(yf + (size_t)r2 * 64 + nt * 8 + c2) = make_float2(v10, v11);
            }
        }
    }
}

// ---- merged GAT gather: warp per dst node, half-warp per edge, fp16 fs rows ----
__global__ void gat_gather3(GatJobs jobs) {
    int w = (blockIdx.x * blockDim.x + threadIdx.x) >> 5;
    int lane = threadIdx.x & 31;
    if (w >= jobs.ntot) return;
    GatJob jb;
    int node;
    if (w < jobs.n0)        { jb = jobs.j[0]; node = w; }
    else if (w < jobs.n01)  { jb = jobs.j[1]; node = w - jobs.n0; }
    else                    { jb = jobs.j[2]; node = w - jobs.n01; }

    int h = lane & 15;
    int half = lane >> 4;
    float4 fdv = ((const float4*)(jb.fd + (size_t)node * 64))[h];
    float4 at  = ((const float4*)jb.attn)[h];
    int b = jb.off[node], e = jb.off[node + 1];
    const __half* fs = jb.fs;
    const int* val = jb.val;

    float denom = 0.f;
    float4 acc = make_float4(0.f, 0.f, 0.f, 0.f);
    int nit = (e - b + 1) >> 1;
    int basej = b + half;

    uint2 A0r = make_uint2(0, 0);
    uint2 A1r = A0r;
    if (nit > 0)
        A0r = ((const uint2*)(fs + (size_t)val[min(basej, e - 1)] * 64))[h];
    if (nit > 1)
        A1r = ((const uint2*)(fs + (size_t)val[min(basej + 2, e - 1)] * 64))[h];

    for (int it = 0; it < nit; it++) {
        uint2 Ar = A0r;
        A0r = A1r;
        if (it + 2 < nit)
            A1r = ((const uint2*)(fs + (size_t)val[min(basej + 2 * (it + 2), e - 1)] * 64))[h];
        __half2* ah = (__half2*)&Ar;
        float2 a01 = __half22float2(ah[0]);
        float2 a23 = __half22float2(ah[1]);
        int j = basej + 2 * it;
        float x0 = a01.x + fdv.x, x1 = a01.y + fdv.y;
        float x2 = a23.x + fdv.z, x3 = a23.y + fdv.w;
        x0 = x0 > 0.f ? x0 : 0.2f * x0;
        x1 = x1 > 0.f ? x1 : 0.2f * x1;
        x2 = x2 > 0.f ? x2 : 0.2f * x2;
        x3 = x3 > 0.f ? x3 : 0.2f * x3;
        float p = x0 * at.x + x1 * at.y + x2 * at.z + x3 * at.w;
#pragma unroll
        for (int o = 8; o; o >>= 1) p += __shfl_xor_sync(0xffffffffu, p, o);
        float ex = (j < e) ? __expf(p) : 0.f;
        denom += ex;
        acc.x += ex * a01.x;
        acc.y += ex * a01.y;
        acc.z += ex * a23.x;
        acc.w += ex * a23.y;
    }
    denom += __shfl_xor_sync(0xffffffffu, denom, 16);
    acc.x += __shfl_xor_sync(0xffffffffu, acc.x, 16);
    acc.y += __shfl_xor_sync(0xffffffffu, acc.y, 16);
    acc.z += __shfl_xor_sync(0xffffffffu, acc.z, 16);
    acc.w += __shfl_xor_sync(0xffffffffu, acc.w, 16);

    if (half == 0) {
        float inv = denom > 0.f ? 1.0f / denom : 0.f;
        float4 bv = ((const float4*)jb.bias)[h];
        float4 o4;
        o4.x = acc.x * inv + bv.x;
        o4.y = acc.y * inv + bv.y;
        o4.z = acc.z * inv + bv.z;
        o4.w = acc.w * inv + bv.w;
        if (jb.resid) {
            float4 rv = ((const float4*)(jb.resid + (size_t)node * jb.rstride))[h];
            o4.x += rv.x; o4.y += rv.y; o4.z += rv.z; o4.w += rv.w;
        }
        ((float4*)(jb.out + (size_t)node * jb.ostride))[h] = o4;
    }
}

// collapse gate MLP + zero the BN sums for this layer
__global__ void gate_prep(const float* __restrict__ W1, const float* __restrict__ b1,
                          const float* __restrict__ W2, const float* __restrict__ b2,
                          float* __restrict__ gout, float* __restrict__ sums) {
    int t = threadIdx.x;          // 256
    if (t < 4) sums[t] = 0.f;
    int i = t >> 7, k = t & 127;
    const float* w1 = W1 + (size_t)i * 128 * 128 + (size_t)k * 128;
    const float* w2 = W2 + i * 128;
    float v = 0.f;
    for (int j = 0; j < 128; j++) v += w1[j] * w2[j];
    gout[i * 132 + k] = v;
    if (k == 0) {
        float c = b2[i];
        const float* bb = b1 + i * 128;
        for (int j = 0; j < 128; j++) c += bb[j] * w2[j];
        gout[i * 132 + 128] = c;
    }
}

__global__ void z_kernel(const float* __restrict__ HU, const float* __restrict__ p,
                         const float* __restrict__ q, const float* __restrict__ gate,
                         float* __restrict__ zinf, float* __restrict__ zint,
                         float* __restrict__ sums, int n) {
    __shared__ float red[8][4];
    int w = (blockIdx.x * blockDim.x + threadIdx.x) >> 5;
    int wl = threadIdx.x >> 5;
    int lane = threadIdx.x & 31;
    float zi = 0.f, zt = 0.f;
    if (w < n) {
        float2 h  = ((const float2*)(HU + (size_t)w * HALL))[lane];
        float2 pv = ((const float2*)(p  + (size_t)w * 64))[lane];
        float2 qv = ((const float2*)(q  + (size_t)w * 64))[lane];
        const float2* vinf = (const float2*)gate;
        const float2* vint = (const float2*)(gate + 132);
        float2 vi0 = vinf[lane], vi1 = vinf[32 + lane];
        float2 vt0 = vint[lane], vt1 = vint[32 + lane];
        zi = h.x * vi0.x + h.y * vi0.y + pv.x * vi1.x + pv.y * vi1.y;
        zt = h.x * vt0.x + h.y * vt0.y + qv.x * vt1.x + qv.y * vt1.y;
    }
#pragma unroll
    for (int off = 16; off; off >>= 1) {
        zi += __shfl_down_sync(0xffffffffu, zi, off);
        zt += __shfl_down_sync(0xffffffffu, zt, off);
    }
    if (lane == 0) {
        if (w < n) {
            zi += gate[128]; zt += gate[132 + 128];
            zinf[w] = zi; zint[w] = zt;
            red[wl][0] = zi; red[wl][1] = zi * zi;
            red[wl][2] = zt; red[wl][3] = zt * zt;
        } else {
            red[wl][0] = red[wl][1] = red[wl][2] = red[wl][3] = 0.f;
        }
    }
    __syncthreads();
    if (threadIdx.x < 4) {
        float s = 0.f;
        for (int k = 0; k < 8; k++) s += red[k][threadIdx.x];
        atomicAdd(sums + threadIdx.x, s);
    }
}

__global__ void gate_apply(const float* __restrict__ HU, float* __restrict__ HUo,
                           const float* __restrict__ p, const float* __restrict__ q,
                           const float* __restrict__ zinf, const float* __restrict__ zint,
                           const float* __restrict__ sums, int n) {
    int w = (blockIdx.x * blockDim.x + threadIdx.x) >> 5;
    int lane = threadIdx.x & 31;
    if (w >= n) return;
    float inv = 1.0f / (float)n;
    float mu0 = sums[0] * inv;
    float var0 = sums[1] * inv - mu0 * mu0;
    float mu1 = sums[2] * inv;
    float var1 = sums[3] * inv - mu1 * mu1;
    float a0 = (zinf[w] - mu0) * rsqrtf(var0 + 1e-5f);
    float a1 = (zint[w] - mu1) * rsqrtf(var1 + 1e-5f);
    a0 = a0 > 0.f ? a0 : 0.01f * a0;
    a1 = a1 > 0.f ? a1 : 0.01f * a1;
    float m = fmaxf(a0, a1);
    float e0 = __expf(a0 - m), e1 = __expf(a1 - m);
    float g0 = e0 / (e0 + e1), g1 = e1 / (e0 + e1);
    float2 pv = ((const float2*)(p + (size_t)w * 64))[lane];
    float2 qv = ((const float2*)(q + (size_t)w * 64))[lane];
    float2 hv = ((const float2*)(HU + (size_t)w * HALL))[lane];
    float2 o;
    o.x = g0 * pv.x + g1 * qv.x + hv.x;
    o.y = g0 * pv.y + g1 * qv.y + hv.y;
    ((float2*)(HUo + (size_t)w * HALL))[lane] = o;
}

// both pos and neg pairs in one launch, fp16 pair tables
__global__ void pair2_kernel(const int* __restrict__ pu, const int* __restrict__ pi,
                             const int* __restrict__ nu, const int* __restrict__ ni,
                             const __half* __restrict__ hu_h,
                             const __half* __restrict__ hi_h,
                             float* __restrict__ out) {
    int w = (blockIdx.x * blockDim.x + threadIdx.x) >> 5;
    int lane = threadIdx.x & 31;
    if (w >= 2 * EPx) return;
    const int* uu = (w < EPx) ? pu : nu;
    const int* ii = (w < EPx) ? pi : ni;
    int idx = (w < EPx) ? w : w - EPx;
    const __half2* hr = (const __half2*)(hu_h + (size_t)uu[idx] * HALL);
    const __half2* ir = (const __half2*)(hi_h + (size_t)ii[idx] * HALL);
    float s = 0.f;
#pragma unroll
    for (int c = 0; c < 3; c++) {
        float2 a = __half22float2(hr[lane + 32 * c]);
        float2 b = __half22float2(ir[lane + 32 * c]);
        s += a.x * b.x + a.y * b.y;
    }
#pragma unroll
    for (int off = 16; off; off >>= 1) s += __shfl_down_sync(0xffffffffu, s, off);
    if (lane == 0) out[w] = s;
}

// ---------------- host ----------------

static void* sym_addr(const void* s) {
    void* p = nullptr;
    cudaGetSymbolAddress(&p, s);
    return p;
}

extern "C" void kernel_launch(void* const* d_in, const int* in_sizes, int n_in,
                              void* d_out, int out_size) {
    int wf = -1, gf = -1;
    for (int i = 0; i < n_in; i++) {
        if (wf < 0 && in_sizes[i] == NUx * EMB) wf = i;   // eu
        if (gf < 0 && in_sizes[i] == ERx) gf = i;         // rate_src
    }
    if (wf < 0) wf = 0;
    if (gf < 0) gf = (wf == 0) ? 18 : 0;
    const float* eu        = (const float*)d_in[wf + 0];
    const float* ei        = (const float*)d_in[wf + 1];
    const float* rate_W    = (const float*)d_in[wf + 2];
    const float* rate_b    = (const float*)d_in[wf + 3];
    const float* rate_attn = (const float*)d_in[wf + 4];
    const float* rate_bias = (const float*)d_in[wf + 5];
    const float* rb_W      = (const float*)d_in[wf + 6];
    const float* rb_b      = (const float*)d_in[wf + 7];
    const float* rb_attn   = (const float*)d_in[wf + 8];
    const float* rb_bias   = (const float*)d_in[wf + 9];
    const float* tr_W      = (const float*)d_in[wf + 10];
    const float* tr_b      = (const float*)d_in[wf + 11];
    const float* tr_attn   = (const float*)d_in[wf + 12];
    const float* tr_bias   = (const float*)d_in[wf + 13];
    const float* attW1     = (const float*)d_in[wf + 14];
    const float* attb1     = (const float*)d_in[wf + 15];
    const float* attW2     = (const float*)d_in[wf + 16];
    const float* attb2     = (const float*)d_in[wf + 17];
    const int* rate_src  = (const int*)d_in[gf + 0];
    const int* rate_dst  = (const int*)d_in[gf + 1];
    const int* trust_src = (const int*)d_in[gf + 2];
    const int* trust_dst = (const int*)d_in[gf + 3];
    const int* pos_u     = (const int*)d_in[gf + 4];
    const int* pos_i     = (const int*)d_in[gf + 5];
    const int* neg_u     = (const int*)d_in[gf + 6];
    const int* neg_i     = (const int*)d_in[gf + 7];

    float* hu_all = (float*)sym_addr(g_hu_all);
    float* hi_all = (float*)sym_addr(g_hi_all);
    __half* hu_h  = (__half*)sym_addr(g_hu_h);
    __half* hi_h  = (__half*)sym_addr(g_hi_h);
    __half* fsU_rate = (__half*)sym_addr(g_fsU_rate);
    __half* fsU_tr   = (__half*)sym_addr(g_fsU_tr);
    __half* fsI_rb   = (__half*)sym_addr(g_fsI_rb);
    float* fdU_rb   = (float*)sym_addr(g_fdU_rb);
    float* fdU_tr   = (float*)sym_addr(g_fdU_tr);
    float* fdI_rate = (float*)sym_addr(g_fdI_rate);
    float* pbuf   = (float*)sym_addr(g_p);
    float* qbuf   = (float*)sym_addr(g_q);
    float* zinf   = (float*)sym_addr(g_zinf);
    float* zint   = (float*)sym_addr(g_zint);
    float* gate   = (float*)sym_addr(g_gate);
    float* sums   = (float*)sym_addr(g_sums);
    int* degU     = (int*)sym_addr(g_degU);
    int* degI     = (int*)sym_addr(g_degI);
    int* degT     = (int*)sym_addr(g_degT);
    int* curU     = (int*)sym_addr(g_curU);
    int* curI     = (int*)sym_addr(g_curI);
    int* curT     = (int*)sym_addr(g_curT);
    int* bsumU    = (int*)sym_addr(g_bsumU);
    int* bsumI    = (int*)sym_addr(g_bsumI);
    int* bsumT    = (int*)sym_addr(g_bsumT);
    int* off_item  = (int*)sym_addr(g_off_item);
    int* off_urate = (int*)sym_addr(g_off_urate);
    int* off_trust = (int*)sym_addr(g_off_trust);
    int* val_item  = (int*)sym_addr(g_val_item);
    int* val_urate = (int*)sym_addr(g_val_urate);
    int* val_trust = (int*)sym_addr(g_val_trust);
    float* out    = (float*)d_out;

    // ---- fused CSR build ----
    int ntotdeg = NUx + NIx + NUx;
    zero3<<<(ntotdeg + 255) / 256, 256>>>(degU, NUx, degI, NIx, degT, NUx);
    count_all<<<(ERx + ETx + 255) / 256, 256>>>(rate_src, rate_dst, trust_dst,
                                                degU, degI, degT);
    scan_bsums_all<<<NBU + NBI + NBU, 256>>>(degU, degI, degT, bsumU, bsumI, bsumT);
    scan_tops_all<<<3, 64>>>(bsumU, bsumI, bsumT, off_urate, off_item, off_trust);
    scan_final_all<<<NBU + NBI + NBU, 256>>>(degU, degI, degT, bsumU, bsumI, bsumT,
                                             off_urate, off_item, off_trust);
    zero3<<<(ntotdeg + 255) / 256, 256>>>(curU, NUx, curI, NIx, curT, NUx);
    scatter_all<<<(ERx + ETx + 255) / 256, 256>>>(rate_src, rate_dst, trust_src, trust_dst,
                                                  off_urate, off_item, off_trust,
                                                  curU, curI, curT,
                                                  val_urate, val_item, val_trust);

    copy_all<<<((NUx + NIx) * 64 + 255) / 256, 256>>>(eu, ei, hu_all, hi_all);

    int nbUg = (NUx + 63) / 64;
    int nbIg = (NIx + 63) / 64;

    for (int l = 0; l < NLAYERS; l++) {
        const float* HU = hu_all + l * 64;        // stride HALL
        float* HUo      = hu_all + (l + 1) * 64;
        const float* HI = hi_all + l * 64;
        float* HIo      = hi_all + (l + 1) * 64;

        const float* rW = rate_W + (size_t)l * 2 * 4096;
        const float* rB = rate_b + (size_t)l * 2 * 64;
        const float* bW = rb_W   + (size_t)l * 2 * 4096;
        const float* bB = rb_b   + (size_t)l * 2 * 64;
        const float* tW = tr_W   + (size_t)l * 2 * 4096;
        const float* tB = tr_b   + (size_t)l * 2 * 64;

        GJobs ju;
        ju.m = 4;
        ju.j[0] = { rW,        rB,        (void*)fsU_rate, 1 };
        ju.j[1] = { bW + 4096, bB + 64,   (void*)fdU_rb,   0 };
        ju.j[2] = { tW,        tB,        (void*)fsU_tr,   1 };
        ju.j[3] = { tW + 4096, tB + 64,   (void*)fdU_tr,   0 };
        GJobs ji;
        ji.m = 2;
        ji.j[0] = { rW + 4096, rB + 64,   (void*)fdI_rate, 0 };
        ji.j[1] = { bW,        bB,        (void*)fsI_rb,   1 };
        ji.j[2] = { nullptr, nullptr, nullptr, 0 };
        ji.j[3] = { nullptr, nullptr, nullptr, 0 };
        gemm64_tc2<<<nbUg + nbIg, 128>>>(HU, NUx, nbUg, ju, HI, NIx, ji);

        GatJobs gj;
        gj.j[0] = { off_item,  val_item,  fsU_rate, fdI_rate,
                    rate_attn + l * 64, rate_bias + l * 64, HI, HALL, HIo, HALL, NIx };
        gj.j[1] = { off_urate, val_urate, fsI_rb,   fdU_rb,
                    rb_attn + l * 64,   rb_bias + l * 64, nullptr, 0, qbuf, 64, NUx };
        gj.j[2] = { off_trust, val_trust, fsU_tr,   fdU_tr,
                    tr_attn + l * 64,   tr_bias + l * 64, nullptr, 0, pbuf, 64, NUx };
        gj.n0 = NIx; gj.n01 = NIx + NUx; gj.ntot = NIx + 2 * NUx;
        gat_gather3<<<(gj.ntot * 32 + 255) / 256, 256>>>(gj);

        gate_prep<<<1, 256>>>(attW1 + (size_t)l * 2 * 128 * 128,
                              attb1 + (size_t)l * 2 * 128,
                              attW2 + (size_t)l * 2 * 128,
                              attb2 + (size_t)l * 2, gate, sums);
        z_kernel<<<(NUx + 7) / 8, 256>>>(HU, pbuf, qbuf, gate, zinf, zint, sums, NUx);
        gate_apply<<<(NUx + 7) / 8, 256>>>(HU, HUo, pbuf, qbuf, zinf, zint, sums, NUx);
    }

    // convert to fp16 pair tables, then compute all 400k dots
    tohalf_pair<<<((NUx + NIx) * HALL / 2 + 255) / 256, 256>>>(hu_all, hi_all, hu_h, hi_h);
    pair2_kernel<<<(2 * EPx + 7) / 8, 256>>>(pos_u, pos_i, neg_u, neg_i,
                                             hu_h, hi_h, out);
}

// round 17
// speedup vs baseline: 1.4532x; 1.0659x over previous
#include <cuda_runtime.h>
#include <cuda_fp16.h>
#include <math.h>

#define EMB 64
#define NLAYERS 2
#define NUx 100000
#define NIx 50000
#define ERx 1000000
#define ETx 800000
#define EPx 200000
#define HALL 192   // EMB*(1+L)
#define NBU 25     // ceil(NUx/4096)
#define NBI 13     // ceil(NIx/4096)

// ---------------- static scratch (no allocations allowed) ----------------
__device__ float g_hu_all[(size_t)NUx * HALL];
__device__ float g_hi_all[(size_t)NIx * HALL];
__device__ __half g_fsU_rate[(size_t)NUx * EMB];
__device__ __half g_fsU_tr[(size_t)NUx * EMB];
__device__ __half g_fsI_rb[(size_t)NIx * EMB];
__device__ float g_fdU_rb[(size_t)NUx * EMB];
__device__ float g_fdU_tr[(size_t)NUx * EMB];
__device__ float g_fdI_rate[(size_t)NIx * EMB];
__device__ float g_p[(size_t)NUx * EMB];
__device__ float g_q[(size_t)NUx * EMB];
__device__ float g_zinf[NUx];
__device__ float g_zint[NUx];
__device__ float g_gate[2][264];
__device__ float g_sums[2][4];
__device__ int g_degU[NUx];
__device__ int g_degI[NIx];
__device__ int g_degT[NUx];
__device__ int g_curU[NUx];
__device__ int g_curI[NIx];
__device__ int g_curT[NUx];
__device__ int g_bsumU[64];
__device__ int g_bsumI[64];
__device__ int g_bsumT[64];
__device__ int g_off_item[NIx + 1];
__device__ int g_off_urate[NUx + 1];
__device__ int g_off_trust[NUx + 1];
__device__ int g_val_item[ERx];
__device__ int g_val_urate[ERx];
__device__ int g_val_trust[ETx];

// ---------------- job descriptors ----------------
struct GJob { const float* W; const float* B; void* Y; int half; };
struct GJobs { GJob j[4]; int m; };

struct GatJob {
    const int* off; const int* val; const __half* fs; const float* fd;
    const float* attn; const float* bias; const float* resid; int rstride;
    float* out; int ostride; int n;
};
struct GatJobs { GatJob j[3]; int n0, n01, ntot; };

static __device__ __forceinline__ unsigned smem_u32(const void* p) {
    return (unsigned)__cvta_generic_to_shared(p);
}

// ---------------- kernels ----------------

// copy eu->hu_all[:,0:64] and ei->hi_all[:,0:64] in one launch
__global__ void copy_all(const float* __restrict__ eu, const float* __restrict__ ei,
                         float* __restrict__ hu, float* __restrict__ hi) {
    int i = blockIdx.x * blockDim.x + threadIdx.x;
    if (i < NUx * 64) {
        int row = i >> 6, j = i & 63;
        hu[(size_t)row * HALL + j] = eu[i];
    } else {
        int k = i - NUx * 64;
        if (k >= NIx * 64) return;
        int row = k >> 6, j = k & 63;
        hi[(size_t)row * HALL + j] = ei[k];
    }
}

// ---- CSR build (fused) ----
__global__ void zero3(int* __restrict__ a, int na, int* __restrict__ b, int nb_,
                      int* __restrict__ c, int nc) {
    int i = blockIdx.x * blockDim.x + threadIdx.x;
    if (i < na) a[i] = 0;
    else if (i < na + nb_) b[i - na] = 0;
    else if (i < na + nb_ + nc) c[i - na - nb_] = 0;
}

__global__ void count_all(const int* __restrict__ rsrc, const int* __restrict__ rdst,
                          const int* __restrict__ tdst,
                          int* __restrict__ degU, int* __restrict__ degI,
                          int* __restrict__ degT) {
    int e = blockIdx.x * blockDim.x + threadIdx.x;
    if (e < ERx) {
        atomicAdd(degU + rsrc[e], 1);
        atomicAdd(degI + rdst[e], 1);
    } else {
        int t = e - ERx;
        if (t < ETx) atomicAdd(degT + tdst[t], 1);
    }
}

__global__ void scan_bsums_all(const int* __restrict__ degU, const int* __restrict__ degI,
                               const int* __restrict__ degT,
                               int* __restrict__ bsumU, int* __restrict__ bsumI,
                               int* __restrict__ bsumT) {
    __shared__ int sh[256];
    int t = threadIdx.x;
    const int* deg; int n; int* bsum; int blk;
    if (blockIdx.x < NBU)            { deg = degU; n = NUx; bsum = bsumU; blk = blockIdx.x; }
    else if (blockIdx.x < NBU + NBI) { deg = degI; n = NIx; bsum = bsumI; blk = blockIdx.x - NBU; }
    else                             { deg = degT; n = NUx; bsum = bsumT; blk = blockIdx.x - NBU - NBI; }
    int base = blk * 4096;
    int s = 0;
#pragma unroll
    for (int i = 0; i < 16; i++) {
        int idx = base + i * 256 + t;
        if (idx < n) s += deg[idx];
    }
    sh[t] = s;
    __syncthreads();
    for (int st = 128; st; st >>= 1) {
        if (t < st) sh[t] += sh[t + st];
        __syncthreads();
    }
    if (t == 0) bsum[blk] = sh[0];
}

__global__ void scan_tops_all(int* __restrict__ bsumU, int* __restrict__ bsumI,
                              int* __restrict__ bsumT,
                              int* __restrict__ offU, int* __restrict__ offI,
                              int* __restrict__ offT) {
    __shared__ int sh[64];
    int t = threadIdx.x;
    int* bsum; int nb; int* total;
    if (blockIdx.x == 0)      { bsum = bsumU; nb = NBU; total = offU + NUx; }
    else if (blockIdx.x == 1) { bsum = bsumI; nb = NBI; total = offI + NIx; }
    else                      { bsum = bsumT; nb = NBU; total = offT + NUx; }
    int v = (t < nb) ? bsum[t] : 0;
    sh[t] = v;
    __syncthreads();
    for (int st = 1; st < 64; st <<= 1) {
        int x = (t >= st) ? sh[t - st] : 0;
        __syncthreads();
        sh[t] += x;
        __syncthreads();
    }
    if (t < nb) bsum[t] = sh[t] - v;
    if (t == 63) *total = sh[63];
}

__global__ void scan_final_all(const int* __restrict__ degU, const int* __restrict__ degI,
                               const int* __restrict__ degT,
                               const int* __restrict__ bsumU, const int* __restrict__ bsumI,
                               const int* __restrict__ bsumT,
                               int* __restrict__ offU, int* __restrict__ offI,
                               int* __restrict__ offT) {
    __shared__ int sh[256];
    int t = threadIdx.x;
    const int* deg; int n; const int* bsum; int* off; int blk;
    if (blockIdx.x < NBU)            { deg = degU; n = NUx; bsum = bsumU; off = offU; blk = blockIdx.x; }
    else if (blockIdx.x < NBU + NBI) { deg = degI; n = NIx; bsum = bsumI; off = offI; blk = blockIdx.x - NBU; }
    else                             { deg = degT; n = NUx; bsum = bsumT; off = offT; blk = blockIdx.x - NBU - NBI; }
    int base = blk * 4096 + t * 16;
    int local[16];
    int s = 0;
#pragma unroll
    for (int i = 0; i < 16; i++) {
        int idx = base + i;
        int d = (idx < n) ? deg[idx] : 0;
        local[i] = d;
        s += d;
    }
    sh[t] = s;
    __syncthreads();
    int v = s;
    for (int st = 1; st < 256; st <<= 1) {
        int x = (t >= st) ? sh[t - st] : 0;
        __syncthreads();
        sh[t] += x;
        __syncthreads();
    }
    int run = bsum[blk] + sh[t] - v;
#pragma unroll
    for (int i = 0; i < 16; i++) {
        int idx = base + i;
        if (idx < n) off[idx] = run;
        run += local[i];
    }
}

__global__ void scatter_all(const int* __restrict__ rsrc, const int* __restrict__ rdst,
                            const int* __restrict__ tsrc, const int* __restrict__ tdst,
                            const int* __restrict__ offU, const int* __restrict__ offI,
                            const int* __restrict__ offT,
                            int* __restrict__ curU, int* __restrict__ curI,
                            int* __restrict__ curT,
                            int* __restrict__ valU, int* __restrict__ valI,
                            int* __restrict__ valT) {
    int e = blockIdx.x * blockDim.x + threadIdx.x;
    if (e < ERx) {
        int s = rsrc[e], d = rdst[e];
        int pI = offI[d] + atomicAdd(curI + d, 1);
        valI[pI] = s;
        int pU = offU[s] + atomicAdd(curU + s, 1);
        valU[pU] = d;
    } else {
        int t = e - ERx;
        if (t >= ETx) return;
        int d = tdst[t];
        int pos = offT[d] + atomicAdd(curT + d, 1);
        valT[pos] = tsrc[t];
    }
}

// ---- merged U+I batched GEMM via fp16 tensor cores ----
__global__ void gemm64_tc2(const float* __restrict__ XU, int nU, int nbUg, GJobs ju,
                           const float* __restrict__ XI, int nI, GJobs ji) {
    __shared__ __half sX[64 * 72];
    __shared__ __half sWh[64 * 72];
    __shared__ float sB[64];
    int tx = threadIdx.x;            // 128
    int warp = tx >> 5, lane = tx & 31;

    const float* X; int n; GJobs jobs; int row0;
    if ((int)blockIdx.x < nbUg) { X = XU; n = nU; jobs = ju; row0 = blockIdx.x * 64; }
    else                        { X = XI; n = nI; jobs = ji; row0 = (blockIdx.x - nbUg) * 64; }

    {
        int r = tx & 63, qu = tx >> 6;
        int row = row0 + r;
        if (row < n) {
            const float4* xr = (const float4*)(X + (size_t)row * HALL) + qu * 8;
#pragma unroll
            for (int j = 0; j < 8; j++) {
                float4 v = xr[j];
                __half2 h0 = __floats2half2_rn(v.x, v.y);
                __half2 h1 = __floats2half2_rn(v.z, v.w);
                *(uint2*)&sX[r * 72 + qu * 32 + j * 4] =
                    make_uint2(*(unsigned*)&h0, *(unsigned*)&h1);
            }
        } else {
#pragma unroll
            for (int j = 0; j < 8; j++)
                *(uint2*)&sX[r * 72 + qu * 32 + j * 4] = make_uint2(0u, 0u);
        }
    }

    int m0 = warp * 16;
    int g = lane >> 2;
    int c2 = (lane & 3) * 2;

    for (int m = 0; m < jobs.m; m++) {
        const float* Wm; const float* Bm; void* Ym; int halfm;
        switch (m) {
            case 0: Wm = jobs.j[0].W; Bm = jobs.j[0].B; Ym = jobs.j[0].Y; halfm = jobs.j[0].half; break;
            case 1: Wm = jobs.j[1].W; Bm = jobs.j[1].B; Ym = jobs.j[1].Y; halfm = jobs.j[1].half; break;
            case 2: Wm = jobs.j[2].W; Bm = jobs.j[2].B; Ym = jobs.j[2].Y; halfm = jobs.j[2].half; break;
            default: Wm = jobs.j[3].W; Bm = jobs.j[3].B; Ym = jobs.j[3].Y; halfm = jobs.j[3].half; break;
        }
        __syncthreads();
        for (int i = tx; i < 1024; i += 128) {
            float4 w = ((const float4*)Wm)[i];
            __half2 h0 = __floats2half2_rn(w.x, w.y);
            __half2 h1 = __floats2half2_rn(w.z, w.w);
            int r = i >> 4, c4 = (i & 15) * 4;
            *(uint2*)&sWh[r * 72 + c4] = make_uint2(*(unsigned*)&h0, *(unsigned*)&h1);
        }
        if (tx < 64) sB[tx] = Bm[tx];
        __syncthreads();

        float acc[8][4];
#pragma unroll
        for (int nt = 0; nt < 8; nt++)
#pragma unroll
            for (int q = 0; q < 4; q++) acc[nt][q] = 0.f;

#pragma unroll
        for (int kc = 0; kc < 4; kc++) {
            unsigned a0, a1, a2, a3;
            {
                int l8 = lane & 7;
                int rsel = (lane & 8) ? 8 : 0;
                int csel = (lane & 16) ? 8 : 0;
                unsigned aaddr = smem_u32(&sX[(m0 + l8 + rsel) * 72 + kc * 16 + csel]);
                asm volatile("ldmatrix.sync.aligned.m8n8.x4.shared.b16 {%0,%1,%2,%3}, [%4];"
                             : "=r"(a0), "=r"(a1), "=r"(a2), "=r"(a3) : "r"(aaddr));
            }
#pragma unroll
            for (int nt = 0; nt < 8; nt++) {
                unsigned b0, b1;
                int krow = kc * 16 + (lane & 15);
                unsigned baddr = smem_u32(&sWh[krow * 72 + nt * 8]);
                asm volatile("ldmatrix.sync.aligned.m8n8.x2.trans.shared.b16 {%0,%1}, [%2];"
                             : "=r"(b0), "=r"(b1) : "r"(baddr));
                asm volatile("mma.sync.aligned.m16n8k16.row.col.f32.f16.f16.f32 "
                             "{%0,%1,%2,%3}, {%4,%5,%6,%7}, {%8,%9}, {%0,%1,%2,%3};"
                             : "+f"(acc[nt][0]), "+f"(acc[nt][1]),
                               "+f"(acc[nt][2]), "+f"(acc[nt][3])
                             : "r"(a0), "r"(a1), "r"(a2), "r"(a3), "r"(b0), "r"(b1));
            }
        }

        int r1 = row0 + m0 + g;
        int r2 = r1 + 8;
#pragma unroll
        for (int nt = 0; nt < 8; nt++) {
            float bv0 = sB[nt * 8 + c2];
            float bv1 = sB[nt * 8 + c2 + 1];
            float v00 = acc[nt][0] + bv0, v01 = acc[nt][1] + bv1;
            float v10 = acc[nt][2] + bv0, v11 = acc[nt][3] + bv1;
            if (halfm) {
                __half* yh = (__half*)Ym;
                if (r1 < n) {
                    __half2 h = __floats2half2_rn(v00, v01);
                    *(__half2*)(yh + (size_t)r1 * 64 + nt * 8 + c2) = h;
                }
                if (r2 < n) {
                    __half2 h = __floats2half2_rn(v10, v11);
                    *(__half2*)(yh + (size_t)r2 * 64 + nt * 8 + c2) = h;
                }
            } else {
                float* yf = (float*)Ym;
                if (r1 < n) *(float2*)(yf + (size_t)r1 * 64 + nt * 8 + c2) = make_float2(v00, v01);
                if (r2 < n) *(float2*)(yf + (size_t)r2 * 64 + nt * 8 + c2) = make_float2(v10, v11);
            }
        }
    }
}

// ---- merged GAT gather: warp per dst node, half-warp per edge, fp16 fs rows ----
__global__ void gat_gather3(GatJobs jobs) {
    int w = (blockIdx.x * blockDim.x + threadIdx.x) >> 5;
    int lane = threadIdx.x & 31;
    if (w >= jobs.ntot) return;
    GatJob jb;
    int node;
    if (w < jobs.n0)        { jb = jobs.j[0]; node = w; }
    else if (w < jobs.n01)  { jb = jobs.j[1]; node = w - jobs.n0; }
    else                    { jb = jobs.j[2]; node = w - jobs.n01; }

    int h = lane & 15;
    int half = lane >> 4;
    float4 fdv = ((const float4*)(jb.fd + (size_t)node * 64))[h];
    float4 at  = ((const float4*)jb.attn)[h];
    int b = jb.off[node], e = jb.off[node + 1];
    const __half* fs = jb.fs;
    const int* val = jb.val;

    float denom = 0.f;
    float4 acc = make_float4(0.f, 0.f, 0.f, 0.f);
    int nit = (e - b + 1) >> 1;
    int basej = b + half;

    uint2 A0r = make_uint2(0, 0);
    uint2 A1r = A0r;
    if (nit > 0)
        A0r = ((const uint2*)(fs + (size_t)val[min(basej, e - 1)] * 64))[h];
    if (nit > 1)
        A1r = ((const uint2*)(fs + (size_t)val[min(basej + 2, e - 1)] * 64))[h];

    for (int it = 0; it < nit; it++) {
        uint2 Ar = A0r;
        A0r = A1r;
        if (it + 2 < nit)
            A1r = ((const uint2*)(fs + (size_t)val[min(basej + 2 * (it + 2), e - 1)] * 64))[h];
        __half2* ah = (__half2*)&Ar;
        float2 a01 = __half22float2(ah[0]);
        float2 a23 = __half22float2(ah[1]);
        int j = basej + 2 * it;
        float x0 = a01.x + fdv.x, x1 = a01.y + fdv.y;
        float x2 = a23.x + fdv.z, x3 = a23.y + fdv.w;
        x0 = x0 > 0.f ? x0 : 0.2f * x0;
        x1 = x1 > 0.f ? x1 : 0.2f * x1;
        x2 = x2 > 0.f ? x2 : 0.2f * x2;
        x3 = x3 > 0.f ? x3 : 0.2f * x3;
        float p = x0 * at.x + x1 * at.y + x2 * at.z + x3 * at.w;
#pragma unroll
        for (int o = 8; o; o >>= 1) p += __shfl_xor_sync(0xffffffffu, p, o);
        float ex = (j < e) ? __expf(p) : 0.f;
        denom += ex;
        acc.x += ex * a01.x;
        acc.y += ex * a01.y;
        acc.z += ex * a23.x;
        acc.w += ex * a23.y;
    }
    denom += __shfl_xor_sync(0xffffffffu, denom, 16);
    acc.x += __shfl_xor_sync(0xffffffffu, acc.x, 16);
    acc.y += __shfl_xor_sync(0xffffffffu, acc.y, 16);
    acc.z += __shfl_xor_sync(0xffffffffu, acc.z, 16);
    acc.w += __shfl_xor_sync(0xffffffffu, acc.w, 16);

    if (half == 0) {
        float inv = denom > 0.f ? 1.0f / denom : 0.f;
        float4 bv = ((const float4*)jb.bias)[h];
        float4 o4;
        o4.x = acc.x * inv + bv.x;
        o4.y = acc.y * inv + bv.y;
        o4.z = acc.z * inv + bv.z;
        o4.w = acc.w * inv + bv.w;
        if (jb.resid) {
            float4 rv = ((const float4*)(jb.resid + (size_t)node * jb.rstride))[h];
            o4.x += rv.x; o4.y += rv.y; o4.z += rv.z; o4.w += rv.w;
        }
        ((float4*)(jb.out + (size_t)node * jb.ostride))[h] = o4;
    }
}

// collapse gate MLPs for BOTH layers in one launch; zero BN sums
__global__ void gate_prep2(const float* __restrict__ attW1, const float* __restrict__ attb1,
                           const float* __restrict__ attW2, const float* __restrict__ attb2,
                           float* __restrict__ gout, float* __restrict__ sums) {
    int l = blockIdx.x;           // layer
    int t = threadIdx.x;          // 256
    if (t < 4) sums[l * 4 + t] = 0.f;
    int i = t >> 7, k = t & 127;
    const float* W1 = attW1 + (size_t)l * 2 * 128 * 128;
    const float* b1 = attb1 + (size_t)l * 2 * 128;
    const float* W2 = attW2 + (size_t)l * 2 * 128;
    const float* b2 = attb2 + (size_t)l * 2;
    float* g = gout + l * 264;
    const float* w1 = W1 + (size_t)i * 128 * 128 + (size_t)k * 128;
    const float* w2 = W2 + i * 128;
    float v = 0.f;
    for (int j = 0; j < 128; j++) v += w1[j] * w2[j];
    g[i * 132 + k] = v;
    if (k == 0) {
        float c = b2[i];
        const float* bb = b1 + i * 128;
        for (int j = 0; j < 128; j++) c += bb[j] * w2[j];
        g[i * 132 + 128] = c;
    }
}

__global__ void z_kernel(const float* __restrict__ HU, const float* __restrict__ p,
                         const float* __restrict__ q, const float* __restrict__ gate,
                         float* __restrict__ zinf, float* __restrict__ zint,
                         float* __restrict__ sums, int n) {
    __shared__ float red[8][4];
    int w = (blockIdx.x * blockDim.x + threadIdx.x) >> 5;
    int wl = threadIdx.x >> 5;
    int lane = threadIdx.x & 31;
    float zi = 0.f, zt = 0.f;
    if (w < n) {
        float2 h  = ((const float2*)(HU + (size_t)w * HALL))[lane];
        float2 pv = ((const float2*)(p  + (size_t)w * 64))[lane];
        float2 qv = ((const float2*)(q  + (size_t)w * 64))[lane];
        const float2* vinf = (const float2*)gate;
        const float2* vint = (const float2*)(gate + 132);
        float2 vi0 = vinf[lane], vi1 = vinf[32 + lane];
        float2 vt0 = vint[lane], vt1 = vint[32 + lane];
        zi = h.x * vi0.x + h.y * vi0.y + pv.x * vi1.x + pv.y * vi1.y;
        zt = h.x * vt0.x + h.y * vt0.y + qv.x * vt1.x + qv.y * vt1.y;
    }
#pragma unroll
    for (int off = 16; off; off >>= 1) {
        zi += __shfl_down_sync(0xffffffffu, zi, off);
        zt += __shfl_down_sync(0xffffffffu, zt, off);
    }
    if (lane == 0) {
        if (w < n) {
            zi += gate[128]; zt += gate[132 + 128];
            zinf[w] = zi; zint[w] = zt;
            red[wl][0] = zi; red[wl][1] = zi * zi;
            red[wl][2] = zt; red[wl][3] = zt * zt;
        } else {
            red[wl][0] = red[wl][1] = red[wl][2] = red[wl][3] = 0.f;
        }
    }
    __syncthreads();
    if (threadIdx.x < 4) {
        float s = 0.f;
        for (int k = 0; k < 8; k++) s += red[k][threadIdx.x];
        atomicAdd(sums + threadIdx.x, s);
    }
}

__global__ void gate_apply(const float* __restrict__ HU, float* __restrict__ HUo,
                           const float* __restrict__ p, const float* __restrict__ q,
                           const float* __restrict__ zinf, const float* __restrict__ zint,
                           const float* __restrict__ sums, int n) {
    int w = (blockIdx.x * blockDim.x + threadIdx.x) >> 5;
    int lane = threadIdx.x & 31;
    if (w >= n) return;
    float inv = 1.0f / (float)n;
    float mu0 = sums[0] * inv;
    float var0 = sums[1] * inv - mu0 * mu0;
    float mu1 = sums[2] * inv;
    float var1 = sums[3] * inv - mu1 * mu1;
    float a0 = (zinf[w] - mu0) * rsqrtf(var0 + 1e-5f);
    float a1 = (zint[w] - mu1) * rsqrtf(var1 + 1e-5f);
    a0 = a0 > 0.f ? a0 : 0.01f * a0;
    a1 = a1 > 0.f ? a1 : 0.01f * a1;
    float m = fmaxf(a0, a1);
    float e0 = __expf(a0 - m), e1 = __expf(a1 - m);
    float g0 = e0 / (e0 + e1), g1 = e1 / (e0 + e1);
    float2 pv = ((const float2*)(p + (size_t)w * 64))[lane];
    float2 qv = ((const float2*)(q + (size_t)w * 64))[lane];
    float2 hv = ((const float2*)(HU + (size_t)w * HALL))[lane];
    float2 o;
    o.x = g0 * pv.x + g1 * qv.x + hv.x;
    o.y = g0 * pv.y + g1 * qv.y + hv.y;
    ((float2*)(HUo + (size_t)w * HALL))[lane] = o;
}

// both pos and neg pairs in one launch
__global__ void pair2_kernel(const int* __restrict__ pu, const int* __restrict__ pi,
                             const int* __restrict__ nu, const int* __restrict__ ni,
                             const float* __restrict__ hu_all, const float* __restrict__ hi_all,
                             float* __restrict__ out) {
    int w = (blockIdx.x * blockDim.x + threadIdx.x) >> 5;
    int lane = threadIdx.x & 31;
    if (w >= 2 * EPx) return;
    const int* uu = (w < EPx) ? pu : nu;
    const int* ii = (w < EPx) ? pi : ni;
    int idx = (w < EPx) ? w : w - EPx;
    const float* hr = hu_all + (size_t)uu[idx] * HALL;
    const float* ir = hi_all + (size_t)ii[idx] * HALL;
    float s = 0.f;
#pragma unroll
    for (int c = 0; c < 6; c++) s += hr[lane + 32 * c] * ir[lane + 32 * c];
#pragma unroll
    for (int off = 16; off; off >>= 1) s += __shfl_down_sync(0xffffffffu, s, off);
    if (lane == 0) out[w] = s;
}

// ---------------- host ----------------

static void* sym_addr(const void* s) {
    void* p = nullptr;
    cudaGetSymbolAddress(&p, s);
    return p;
}

extern "C" void kernel_launch(void* const* d_in, const int* in_sizes, int n_in,
                              void* d_out, int out_size) {
    int wf = -1, gf = -1;
    for (int i = 0; i < n_in; i++) {
        if (wf < 0 && in_sizes[i] == NUx * EMB) wf = i;   // eu
        if (gf < 0 && in_sizes[i] == ERx) gf = i;         // rate_src
    }
    if (wf < 0) wf = 0;
    if (gf < 0) gf = (wf == 0) ? 18 : 0;
    const float* eu        = (const float*)d_in[wf + 0];
    const float* ei        = (const float*)d_in[wf + 1];
    const float* rate_W    = (const float*)d_in[wf + 2];
    const float* rate_b    = (const float*)d_in[wf + 3];
    const float* rate_attn = (const float*)d_in[wf + 4];
    const float* rate_bias = (const float*)d_in[wf + 5];
    const float* rb_W      = (const float*)d_in[wf + 6];
    const float* rb_b      = (const float*)d_in[wf + 7];
    const float* rb_attn   = (const float*)d_in[wf + 8];
    const float* rb_bias   = (const float*)d_in[wf + 9];
    const float* tr_W      = (const float*)d_in[wf + 10];
    const float* tr_b      = (const float*)d_in[wf + 11];
    const float* tr_attn   = (const float*)d_in[wf + 12];
    const float* tr_bias   = (const float*)d_in[wf + 13];
    const float* attW1     = (const float*)d_in[wf + 14];
    const float* attb1     = (const float*)d_in[wf + 15];
    const float* attW2     = (const float*)d_in[wf + 16];
    const float* attb2     = (const float*)d_in[wf + 17];
    const int* rate_src  = (const int*)d_in[gf + 0];
    const int* rate_dst  = (const int*)d_in[gf + 1];
    const int* trust_src = (const int*)d_in[gf + 2];
    const int* trust_dst = (const int*)d_in[gf + 3];
    const int* pos_u     = (const int*)d_in[gf + 4];
    const int* pos_i     = (const int*)d_in[gf + 5];
    const int* neg_u     = (const int*)d_in[gf + 6];
    const int* neg_i     = (const int*)d_in[gf + 7];

    float* hu_all = (float*)sym_addr(g_hu_all);
    float* hi_all = (float*)sym_addr(g_hi_all);
    __half* fsU_rate = (__half*)sym_addr(g_fsU_rate);
    __half* fsU_tr   = (__half*)sym_addr(g_fsU_tr);
    __half* fsI_rb   = (__half*)sym_addr(g_fsI_rb);
    float* fdU_rb   = (float*)sym_addr(g_fdU_rb);
    float* fdU_tr   = (float*)sym_addr(g_fdU_tr);
    float* fdI_rate = (float*)sym_addr(g_fdI_rate);
    float* pbuf   = (float*)sym_addr(g_p);
    float* qbuf   = (float*)sym_addr(g_q);
    float* zinf   = (float*)sym_addr(g_zinf);
    float* zint   = (float*)sym_addr(g_zint);
    float* gate   = (float*)sym_addr(g_gate);
    float* sums   = (float*)sym_addr(g_sums);
    int* degU     = (int*)sym_addr(g_degU);
    int* degI     = (int*)sym_addr(g_degI);
    int* degT     = (int*)sym_addr(g_degT);
    int* curU     = (int*)sym_addr(g_curU);
    int* curI     = (int*)sym_addr(g_curI);
    int* curT     = (int*)sym_addr(g_curT);
    int* bsumU    = (int*)sym_addr(g_bsumU);
    int* bsumI    = (int*)sym_addr(g_bsumI);
    int* bsumT    = (int*)sym_addr(g_bsumT);
    int* off_item  = (int*)sym_addr(g_off_item);
    int* off_urate = (int*)sym_addr(g_off_urate);
    int* off_trust = (int*)sym_addr(g_off_trust);
    int* val_item  = (int*)sym_addr(g_val_item);
    int* val_urate = (int*)sym_addr(g_val_urate);
    int* val_trust = (int*)sym_addr(g_val_trust);
    float* out    = (float*)d_out;

    // ---- fused CSR build ----
    int ntotdeg = NUx + NIx + NUx;
    zero3<<<(ntotdeg + 255) / 256, 256>>>(degU, NUx, degI, NIx, degT, NUx);
    count_all<<<(ERx + ETx + 255) / 256, 256>>>(rate_src, rate_dst, trust_dst,
                                                degU, degI, degT);
    scan_bsums_all<<<NBU + NBI + NBU, 256>>>(degU, degI, degT, bsumU, bsumI, bsumT);
    scan_tops_all<<<3, 64>>>(bsumU, bsumI, bsumT, off_urate, off_item, off_trust);
    scan_final_all<<<NBU + NBI + NBU, 256>>>(degU, degI, degT, bsumU, bsumI, bsumT,
                                             off_urate, off_item, off_trust);
    zero3<<<(ntotdeg + 255) / 256, 256>>>(curU, NUx, curI, NIx, curT, NUx);
    scatter_all<<<(ERx + ETx + 255) / 256, 256>>>(rate_src, rate_dst, trust_src, trust_dst,
                                                  off_urate, off_item, off_trust,
                                                  curU, curI, curT,
                                                  val_urate, val_item, val_trust);

    copy_all<<<((NUx + NIx) * 64 + 255) / 256, 256>>>(eu, ei, hu_all, hi_all);
    // both layers' gate vectors in one launch (independent of everything above)
    gate_prep2<<<2, 256>>>(attW1, attb1, attW2, attb2, gate, sums);

    int nbUg = (NUx + 63) / 64;
    int nbIg = (NIx + 63) / 64;

    for (int l = 0; l < NLAYERS; l++) {
        const float* HU = hu_all + l * 64;        // stride HALL
        float* HUo      = hu_all + (l + 1) * 64;
        const float* HI = hi_all + l * 64;
        float* HIo      = hi_all + (l + 1) * 64;

        const float* rW = rate_W + (size_t)l * 2 * 4096;
        const float* rB = rate_b + (size_t)l * 2 * 64;
        const float* bW = rb_W   + (size_t)l * 2 * 4096;
        const float* bB = rb_b   + (size_t)l * 2 * 64;
        const float* tW = tr_W   + (size_t)l * 2 * 4096;
        const float* tB = tr_b   + (size_t)l * 2 * 64;

        GJobs ju;
        ju.m = 4;
        ju.j[0] = { rW,        rB,        (void*)fsU_rate, 1 };
        ju.j[1] = { bW + 4096, bB + 64,   (void*)fdU_rb,   0 };
        ju.j[2] = { tW,        tB,        (void*)fsU_tr,   1 };
        ju.j[3] = { tW + 4096, tB + 64,   (void*)fdU_tr,   0 };
        GJobs ji;
        ji.m = 2;
        ji.j[0] = { rW + 4096, rB + 64,   (void*)fdI_rate, 0 };
        ji.j[1] = { bW,        bB,        (void*)fsI_rb,   1 };
        ji.j[2] = { nullptr, nullptr, nullptr, 0 };
        ji.j[3] = { nullptr, nullptr, nullptr, 0 };
        gemm64_tc2<<<nbUg + nbIg, 128>>>(HU, NUx, nbUg, ju, HI, NIx, ji);

        GatJobs gj;
        gj.j[0] = { off_item,  val_item,  fsU_rate, fdI_rate,
                    rate_attn + l * 64, rate_bias + l * 64, HI, HALL, HIo, HALL, NIx };
        gj.j[1] = { off_urate, val_urate, fsI_rb,   fdU_rb,
                    rb_attn + l * 64,   rb_bias + l * 64, nullptr, 0, qbuf, 64, NUx };
        gj.j[2] = { off_trust, val_trust, fsU_tr,   fdU_tr,
                    tr_attn + l * 64,   tr_bias + l * 64, nullptr, 0, pbuf, 64, NUx };
        gj.n0 = NIx; gj.n01 = NIx + NUx; gj.ntot = NIx + 2 * NUx;
        gat_gather3<<<(gj.ntot * 32 + 255) / 256, 256>>>(gj);

        z_kernel<<<(NUx + 7) / 8, 256>>>(HU, pbuf, qbuf, gate + l * 264,
                                         zinf, zint, sums + l * 4, NUx);
        gate_apply<<<(NUx + 7) / 8, 256>>>(HU, HUo, pbuf, qbuf, zinf, zint,
                                           sums + l * 4, NUx);
    }

    pair2_kernel<<<(2 * EPx + 7) / 8, 256>>>(pos_u, pos_i, neg_u, neg_i,
                                             hu_all, hi_all, out);
}